// round 16
// baseline (speedup 1.0000x reference)
#include <cuda_runtime.h>
#include <cuda_fp16.h>
#include <cstdint>

// ---------------------------------------------------------------------------
// ConvTemporalGraphical
// K1: fp16 1-term mma.sync GEMM, cp.async 2-stage pipeline, 3 blocks/SM
//     (24 warps/SM for latency hiding; cross-block desync fills bubbles).
// K2: reduce 296 partials + b0 + ELU -> h0
// K3: h1 = ELU(h0@W1+b1)  (256 blocks)
// K4: gconv with fused logits+softmax prologue, 2 channels per thread.
// ---------------------------------------------------------------------------

#define K_DIM 204800
#define M_DIM 32
#define N_DIM 256
#define SPLIT 296              // = 2 * 148 SMs
#define TILES_TOTAL 6400       // K / 32

__device__ float g_partial[SPLIT * M_DIM * N_DIM];   // 9.7 MB
__device__ float g_h0[M_DIM * N_DIM];
__device__ float g_h1[M_DIM * N_DIM];

typedef unsigned long long u64;

__device__ __forceinline__ float elu(float v) { return v > 0.0f ? v : expm1f(v); }

__device__ __forceinline__ u64 pack2(float lo, float hi) {
    u64 r; asm("mov.b64 %0, {%1, %2};" : "=l"(r) : "f"(lo), "f"(hi)); return r;
}
__device__ __forceinline__ void unpack2(u64 v, float& lo, float& hi) {
    asm("mov.b64 {%0, %1}, %2;" : "=f"(lo), "=f"(hi) : "l"(v));
}
__device__ __forceinline__ void ffma2(u64& d, u64 a, u64 b) {
    asm("fma.rn.f32x2 %0, %1, %2, %0;" : "+l"(d) : "l"(a), "l"(b));
}
__device__ __forceinline__ uint32_t smem_u32(const void* p) {
    uint32_t a;
    asm("{ .reg .u64 t; cvta.to.shared.u64 t, %1; cvt.u32.u64 %0, t; }" : "=r"(a) : "l"(p));
    return a;
}
__device__ __forceinline__ uint32_t packh2(float a, float b) {
    __half2 h = __floats2half2_rn(a, b);
    return *reinterpret_cast<uint32_t*>(&h);
}
__device__ __forceinline__ void mma_f16(float* d, const uint32_t* a,
                                        uint32_t b0, uint32_t b1) {
    asm volatile(
        "mma.sync.aligned.m16n8k16.row.col.f32.f16.f16.f32 "
        "{%0,%1,%2,%3}, {%4,%5,%6,%7}, {%8,%9}, {%0,%1,%2,%3};"
        : "+f"(d[0]), "+f"(d[1]), "+f"(d[2]), "+f"(d[3])
        : "r"(a[0]), "r"(a[1]), "r"(a[2]), "r"(a[3]), "r"(b0), "r"(b1));
}

// smem layout (fp32 words)
#define BPADW 260
#define BSTW  (32 * BPADW)             // 8320 words per B stage
#define NSTG  2
#define AOFFW (NSTG * BSTW)            // 16640
#define AMP   36                       // A pair-row m-stride (uint2 units)
#define APLW  (8 * AMP * 2)            // words per A plane = 576
#define SMEM_WORDS (AOFFW + 2 * APLW)  // 17792 words = 71168 B  (x3 = 213.5 KB)

// ---------------------------------------------------------------------------
// K1: cp.async 2-stage pipeline, 3 blocks/SM; fp16 1-term compute.
// iter i: wait_group 1 (B(i) done); sync; stsA(i+1); ldgA(i+2); compute(i);
//         sync; issueB(i+2) into slot i%2; commit.
// ---------------------------------------------------------------------------
__global__ __launch_bounds__(256, 3)
void gemm0_mma(const float* __restrict__ x, const float* __restrict__ W0) {
    extern __shared__ uint32_t sm[];
    const uint32_t sb = smem_u32(sm);

    const int tid  = threadIdx.x;
    const int w    = tid >> 5;
    const int lane = tid & 31;
    const int g    = lane >> 2;    // 0..7
    const int tg   = lane & 3;     // 0..3
    const int nbase = w * 32;

    const int tl_beg = (int)(((long)blockIdx.x       * TILES_TOTAL) / SPLIT);
    const int tl_end = (int)(((long)(blockIdx.x + 1) * TILES_TOTAL) / SPLIT);
    const int T = tl_end - tl_beg;   // 21 or 22

    const int am[2]  = { (0*256+tid) >> 4, (1*256+tid) >> 4 };
    const int akp[2] = { (0*256+tid) & 15, (1*256+tid) & 15 };

    float d[2][4][4];
#pragma unroll
    for (int mt = 0; mt < 2; mt++)
#pragma unroll
        for (int j = 0; j < 4; j++)
#pragma unroll
            for (int r = 0; r < 4; r++) d[mt][j][r] = 0.0f;

    auto issueB = [&](int tl, int slot) {
        const float* gsrc = W0 + (long)tl * 32 * N_DIM;
        const uint32_t sdst = sb + (uint32_t)(slot * BSTW) * 4u;
#pragma unroll
        for (int it = 0; it < 8; it++) {
            const int id  = it * 256 + tid;
            const int row = id >> 6;
            const int col = (id & 63) * 4;
            const uint32_t dst = sdst + (uint32_t)(row * BPADW + col) * 4u;
            const float* src = gsrc + row * N_DIM + col;
            asm volatile("cp.async.cg.shared.global [%0], [%1], 16;"
                         :: "r"(dst), "l"(src));
        }
    };

    float2 ar[2];
    auto ldgA = [&](int tl) {
#pragma unroll
        for (int it = 0; it < 2; it++)
            ar[it] = *(const float2*)(x + (long)am[it] * K_DIM + tl * 32 + 2 * akp[it]);
    };
    // A layout: plane[q][m] uint2 = {kp = s*8+tq, kp+4}, q = s*4+tq
    auto stsA = [&](int slot) {
        uint32_t* Ah = sm + AOFFW + slot * APLW;
#pragma unroll
        for (int it = 0; it < 2; it++) {
            const uint32_t h = packh2(ar[it].x, ar[it].y);
            const int kp = akp[it];
            const int s_ = kp >> 3;
            const int tq = kp & 3;
            const int hf = (kp >> 2) & 1;
            Ah[((s_ * 4 + tq) * AMP + am[it]) * 2 + hf] = h;
        }
    };

    // prologue: B groups for tiles 0,1 in flight; A(0) staged; A(1) in regs
    issueB(tl_beg, 0);
    asm volatile("cp.async.commit_group;");
    issueB(tl_beg + 1, 1);
    asm volatile("cp.async.commit_group;");
    ldgA(tl_beg);
    stsA(0);
    ldgA(tl_beg + 1);

    for (int i = 0; i < T; i++) {
        asm volatile("cp.async.wait_group 1;");   // B(i) complete
        __syncthreads();                          // all past compute(i-1); A(i),B(i) visible

        if (i + 1 < T) stsA((i + 1) & 1);         // slot != i&1, safe during compute(i)
        if (i + 2 < T) ldgA(tl_beg + i + 2);

        // ---- compute tile i ----
        const float*    Bb = (const float*)(sm) + (i & 1) * BSTW;
        const uint32_t* Ah = sm + AOFFW + (i & 1) * APLW;

#pragma unroll
        for (int s = 0; s < 2; s++) {
            const int q   = s * 4 + tg;
            const int kp0 = s * 8 + tg;

            uint32_t ah[2][4];
#pragma unroll
            for (int mt = 0; mt < 2; mt++) {
                const int m0 = mt * 16 + g;
                const uint2 pa0 = *(const uint2*)(Ah + (q * AMP + m0) * 2);
                const uint2 pa1 = *(const uint2*)(Ah + (q * AMP + m0 + 8) * 2);
                ah[mt][0] = pa0.x; ah[mt][2] = pa0.y;
                ah[mt][1] = pa1.x; ah[mt][3] = pa1.y;
            }

            const int kr0 = 4 * kp0;       // careful: rows are 2*kp0 in row units
            const int r0i = 2 * kp0;
            const int r1i = r0i + 8;
            const float4 r0 = *(const float4*)(Bb + r0i * BPADW + nbase + 4 * g);
            const float4 r1 = *(const float4*)(Bb + (r0i + 1) * BPADW + nbase + 4 * g);
            const float4 r2 = *(const float4*)(Bb + r1i * BPADW + nbase + 4 * g);
            const float4 r3 = *(const float4*)(Bb + (r1i + 1) * BPADW + nbase + 4 * g);
            uint32_t bh[4][2];
            bh[0][0] = packh2(r0.x, r1.x); bh[0][1] = packh2(r2.x, r3.x);
            bh[1][0] = packh2(r0.y, r1.y); bh[1][1] = packh2(r2.y, r3.y);
            bh[2][0] = packh2(r0.z, r1.z); bh[2][1] = packh2(r2.z, r3.z);
            bh[3][0] = packh2(r0.w, r1.w); bh[3][1] = packh2(r2.w, r3.w);
            (void)kr0;

#pragma unroll
            for (int j = 0; j < 4; j++)
#pragma unroll
                for (int mt = 0; mt < 2; mt++)
                    mma_f16(d[mt][j], ah[mt], bh[j][0], bh[j][1]);
        }

        __syncthreads();                          // compute(i) done before B slot reuse
        if (i + 2 < T) issueB(tl_beg + i + 2, i & 1);
        asm volatile("cp.async.commit_group;");
    }

    // epilogue: tile j col (2tg+delta) -> logical n = nbase + 4*(2tg+delta)+j
    float* po = g_partial + blockIdx.x * (M_DIM * N_DIM);
#pragma unroll
    for (int mt = 0; mt < 2; mt++) {
#pragma unroll
        for (int j = 0; j < 4; j++) {
            const int m0 = mt * 16 + g;
            const int c0 = nbase + 8 * tg + j;
            po[m0 * N_DIM + c0]           = d[mt][j][0];
            po[m0 * N_DIM + c0 + 4]       = d[mt][j][1];
            po[(m0 + 8) * N_DIM + c0]     = d[mt][j][2];
            po[(m0 + 8) * N_DIM + c0 + 4] = d[mt][j][3];
        }
    }
}

// ---------------------------------------------------------------------------
// K2: reduce 296 partials (fixed order -> deterministic) + b0 + ELU.
// ---------------------------------------------------------------------------
__global__ __launch_bounds__(256)
void reduce_kernel(const float* __restrict__ b0) {
    __shared__ float red[8][32];
    const int m  = blockIdx.x >> 3;
    const int nc = (blockIdx.x & 7) * 32;
    const int nl = threadIdx.x & 31;
    const int sl = threadIdx.x >> 5;
    const int n  = nc + nl;

    float s = 0.0f;
    const float* p = g_partial + (sl * 37) * (M_DIM * N_DIM) + m * N_DIM + n;
#pragma unroll
    for (int i = 0; i < 37; i++) s += p[i * (M_DIM * N_DIM)];
    red[sl][nl] = s;
    __syncthreads();
    if (sl == 0) {
        float a = b0[n];
#pragma unroll
        for (int j = 0; j < 8; j++) a += red[j][nl];
        g_h0[m * N_DIM + n] = elu(a);
    }
}

// ---------------------------------------------------------------------------
// K3: h1 = ELU(h0 @ W1 + b1). 256 blocks: (m, 32-wide n chunk).
// ---------------------------------------------------------------------------
__global__ __launch_bounds__(256)
void mlp1_kernel(const float* __restrict__ W1, const float* __restrict__ b1) {
    __shared__ float red[8][32];
    const int m  = blockIdx.x >> 3;
    const int nc = (blockIdx.x & 7) * 32;
    const int nl = threadIdx.x & 31;
    const int sl = threadIdx.x >> 5;
    const int n  = nc + nl;

    float s = 0.0f;
    const float* hr = g_h0 + m * N_DIM;
#pragma unroll
    for (int k = 0; k < 32; k++)
        s += hr[sl * 32 + k] * W1[(sl * 32 + k) * 256 + n];
    red[sl][nl] = s;
    __syncthreads();
    if (sl == 0) {
        float a = b1[n];
#pragma unroll
        for (int j = 0; j < 8; j++) a += red[j][nl];
        g_h1[m * N_DIM + n] = elu(a);
    }
}

// ---------------------------------------------------------------------------
// K4: gconv with fused logits+softmax prologue. 128 thr = 4 warps.
// ---------------------------------------------------------------------------
__global__ __launch_bounds__(128)
void gconv_kernel(const float* __restrict__ x, const float* __restrict__ A,
                  const float* __restrict__ W2, const float* __restrict__ b2,
                  float* __restrict__ out) {
    __shared__ __align__(16) float ASs[4][650];   // 10.4 KB
    __shared__ float buf[64 * 101];               // 25.9 KB (xs then os)
    __shared__ float lgs[4];
    __shared__ float wsm[4];
    const int tid = threadIdx.x;
    const int n   = blockIdx.y;
    const int t0  = blockIdx.x * 4;

    // ---- fused softmax ----
    {
        const int e    = tid >> 5;
        const int lane = tid & 31;
        float s = 0.0f;
        const float* hr = g_h1 + n * N_DIM;
#pragma unroll
        for (int k = lane; k < 256; k += 32) s += hr[k] * W2[k * 4 + e];
#pragma unroll
        for (int o = 16; o; o >>= 1) s += __shfl_xor_sync(0xffffffffu, s, o);
        if (lane == 0) lgs[e] = s + b2[e];
    }
    __syncthreads();
    if (tid < 4) {
        const float l0 = lgs[0], l1 = lgs[1], l2 = lgs[2], l3 = lgs[3];
        const float mx = fmaxf(fmaxf(l0, l1), fmaxf(l2, l3));
        const float e0 = expf(l0 - mx), e1 = expf(l1 - mx);
        const float e2 = expf(l2 - mx), e3 = expf(l3 - mx);
        const float inv = 1.0f / (e0 + e1 + e2 + e3);
        const float ev = (tid == 0) ? e0 : (tid == 1) ? e1 : (tid == 2) ? e2 : e3;
        wsm[tid] = ev * inv;
    }
    __syncthreads();

    const float w0 = wsm[0], w1 = wsm[1], w2 = wsm[2], w3 = wsm[3];

    for (int idx = tid; idx < 2500; idx += 128) {
        const int grp = idx / 625;
        const int j   = idx - grp * 625;
        const int v   = j / 25;
        const int ww  = j - v * 25;
        const float* At = A + (t0 + grp) * 625 + j;
        ASs[grp][v * 26 + ww] = w0 * At[0]
                              + w1 * At[1 * 128 * 625]
                              + w2 * At[2 * 128 * 625]
                              + w3 * At[3 * 128 * 625];
    }

    const float* xb = x + n * K_DIM + t0 * 25;
#pragma unroll 10
    for (int u = 0; u < 50; u++) {
        const int idx = u * 128 + tid;
        const int c = idx / 100;
        const int j = idx - c * 100;
        const int grp = j / 25;
        const int v   = j - grp * 25;
        buf[grp * 1600 + c * 25 + v] = xb[c * 3200 + j];
    }
    __syncthreads();

    const int grp = tid >> 5;
    const int c0  = tid & 31;
    const float* xg = &buf[grp * 1600];
    const float* Ab = &ASs[grp][0];

    u64 accA[12], accB[12];
#pragma unroll
    for (int p = 0; p < 12; p++) { accA[p] = 0ull; accB[p] = 0ull; }
    float a24 = 0.0f, b24 = 0.0f;

#pragma unroll
    for (int v = 0; v < 25; v++) {
        const float x0 = xg[c0 * 25 + v];
        const float x1 = xg[(c0 + 32) * 25 + v];
        const u64 g0 = pack2(x0, x0);
        const u64 g1 = pack2(x1, x1);
        const float* row = Ab + v * 26;
#pragma unroll
        for (int p = 0; p < 12; p++) {
            const u64 wv = *(const u64*)(row + 2 * p);
            ffma2(accA[p], g0, wv);
            ffma2(accB[p], g1, wv);
        }
        const float aw = row[24];
        a24 += x0 * aw;
        b24 += x1 * aw;
    }

    __syncthreads();

    {
        float* osA = &buf[c0 * 101 + grp * 25];
        float* osB = &buf[(c0 + 32) * 101 + grp * 25];
#pragma unroll
        for (int p = 0; p < 12; p++) {
            float lo, hi;
            unpack2(accA[p], lo, hi);
            osA[2 * p] = lo; osA[2 * p + 1] = hi;
            unpack2(accB[p], lo, hi);
            osB[2 * p] = lo; osB[2 * p + 1] = hi;
        }
        osA[24] = a24;
        osB[24] = b24;
    }
    __syncthreads();

    float* ob = out + n * K_DIM + t0 * 25;
#pragma unroll 10
    for (int u = 0; u < 50; u++) {
        const int idx = u * 128 + tid;
        const int c2 = idx / 100;
        const int j  = idx - c2 * 100;
        ob[c2 * 3200 + j] = buf[c2 * 101 + j];
    }
}

// ---------------------------------------------------------------------------
extern "C" void kernel_launch(void* const* d_in, const int* in_sizes, int n_in,
                              void* d_out, int out_size) {
    const float* x  = (const float*)d_in[0];
    const float* W0 = (const float*)d_in[1];
    const float* b0 = (const float*)d_in[2];
    const float* W1 = (const float*)d_in[3];
    const float* b1 = (const float*)d_in[4];
    const float* W2 = (const float*)d_in[5];
    const float* b2 = (const float*)d_in[6];
    const float* A  = (const float*)d_in[7];
    float* out = (float*)d_out;

    cudaFuncSetAttribute(gemm0_mma, cudaFuncAttributeMaxDynamicSharedMemorySize,
                         SMEM_WORDS * 4);

    gemm0_mma<<<SPLIT, 256, SMEM_WORDS * 4>>>(x, W0);
    reduce_kernel<<<256, 256>>>(b0);
    mlp1_kernel<<<256, 256>>>(W1, b1);
    gconv_kernel<<<dim3(32, 32), 128>>>(x, A, W2, b2, out);
}